// round 14
// baseline (speedup 1.0000x reference)
#include <cuda_runtime.h>
#include <cuda_bf16.h>
#include <cstdint>
#include <math.h>

#define BB 4
#define CC 768
#define FF 256
#define N0 1024

// ---------------- scratch ----------------
__device__ float g_x0 [BB*FF*N0];
__device__ float g_x1 [BB*FF*N0];
__device__ float g_off1[BB*32*N0];
__device__ float g_off2[BB*32*4*N0];
__device__ float g_c1 [BB*FF*4*N0];
__device__ float g_P  [BB*9*16*N0];            // head partial planes
__device__ uint32_t g_up1H[BB*128*4*N0];
__device__ uint32_t g_up1L[BB*128*4*N0];
__device__ uint32_t g_up2H[BB*128*16*N0];
__device__ uint32_t g_up2L[BB*128*16*N0];
__device__ uint32_t g_w1H[294912], g_w1L[294912];
__device__ uint32_t g_w2H[294912], g_w2L[294912];
__device__ uint32_t g_pwH[393216], g_pwL[393216];
__device__ float g_zero4[4] = {0.f, 0.f, 0.f, 0.f};

// ---------------- helpers ----------------
__device__ __forceinline__ uint32_t smem_u32(const void* p) {
    uint32_t a; asm("{ .reg .u64 t; cvta.to.shared.u64 t, %1; cvt.u32.u64 %0, t; }"
                    : "=r"(a) : "l"(p)); return a;
}
#define SWZ(x)   ((uint32_t)(x) ^ ((((uint32_t)(x)) >> 3) & 0x70u))
#define SWZ64(x) ((uint32_t)(x) ^ ((((uint32_t)(x)) >> 3) & 0x30u))

__device__ __forceinline__ void ldsm_x4(uint32_t (&r)[4], uint32_t addr) {
    asm volatile("ldmatrix.sync.aligned.m8n8.x4.shared.b16 {%0,%1,%2,%3}, [%4];"
        : "=r"(r[0]), "=r"(r[1]), "=r"(r[2]), "=r"(r[3]) : "r"(addr));
}
__device__ __forceinline__ void mma16816(float* d, const uint32_t* a, const uint32_t* b) {
    asm volatile("mma.sync.aligned.m16n8k16.row.col.f32.bf16.bf16.f32 "
        "{%0,%1,%2,%3}, {%4,%5,%6,%7}, {%8,%9}, {%0,%1,%2,%3};"
        : "+f"(d[0]), "+f"(d[1]), "+f"(d[2]), "+f"(d[3])
        : "r"(a[0]), "r"(a[1]), "r"(a[2]), "r"(a[3]), "r"(b[0]), "r"(b[1]));
}
__device__ __forceinline__ void split_bf16(float v, __nv_bfloat16& h, __nv_bfloat16& l) {
    h = __float2bfloat16(v);
    l = __float2bfloat16(v - __bfloat162float(h));
}
__device__ __forceinline__ uint32_t pack2(__nv_bfloat16 a, __nv_bfloat16 b) {
    __nv_bfloat162 t = __halves2bfloat162(a, b);
    return *(uint32_t*)&t;
}
#define CP_A4(dst, src)  asm volatile("cp.async.ca.shared.global [%0], [%1], 4;"  :: "r"(dst), "l"(src))
#define CP_A16(dst, src) asm volatile("cp.async.cg.shared.global [%0], [%1], 16;" :: "r"(dst), "l"(src))
#define CP_COMMIT() asm volatile("cp.async.commit_group;" ::: "memory")
#define CP_WAIT0()  asm volatile("cp.async.wait_group 0;" ::: "memory")
#define CP_WAIT1()  asm volatile("cp.async.wait_group 1;" ::: "memory")

// ---------------- weight pre-pack: conv OIHW -> [ch36][co][c2 32] hi/lo u32 ----------------
__global__ __launch_bounds__(256) void k_prep_w(const float* __restrict__ w1,
                                                const float* __restrict__ w2) {
    int idx = blockIdx.x * 256 + threadIdx.x;
    int which = idx >= 294912;
    int t = which ? idx - 294912 : idx;
    int c2 = t & 31, co = (t >> 5) & 255, ch = t >> 13;
    int kpos = ch >> 2, ci = (ch & 3) * 64 + 2 * c2;
    const float* w = which ? w2 : w1;
    float v0 = w[(co * 256 + ci) * 9 + kpos];
    float v1 = w[(co * 256 + ci + 1) * 9 + kpos];
    __nv_bfloat16 h0, l0, h1, l1;
    split_bf16(v0, h0, l0); split_bf16(v1, h1, l1);
    (which ? g_w2H : g_w1H)[t] = pack2(h0, h1);
    (which ? g_w2L : g_w1L)[t] = pack2(l0, l1);
}

// ---------------- fusion weight pre-pack ----------------
__global__ __launch_bounds__(256) void k_prep_pw(const float* __restrict__ pw) {
    int t = blockIdx.x * 256 + threadIdx.x;
    int c2 = t & 31, co = (t >> 5) & 255, r = t >> 13;
    int l = r / 12, ch = r - l * 12;
    int c = ch * 64 + 2 * c2;
    float v0 = pw[((size_t)l * CC + c) * FF + co];
    float v1 = pw[((size_t)l * CC + c + 1) * FF + co];
    __nv_bfloat16 h0, l0, h1, l1;
    split_bf16(v0, h0, l0); split_bf16(v1, h1, l1);
    g_pwH[t] = pack2(h0, h1);
    g_pwL[t] = pack2(l0, l1);
}

// ---------------- fusion GEMM: HMMA bf16 3-term, GELU + weighted layer sum ----------------
#define FM_SMEM (49152 + 1024)
__global__ __launch_bounds__(256) void k_fusion_mma(
    const float* __restrict__ fa, const float* __restrict__ fb,
    const float* __restrict__ fc, const float* __restrict__ fd,
    const float* __restrict__ lwp)
{
    extern __shared__ char smem_raw[];
    const uint32_t sb0 = smem_u32(smem_raw);
    const uint32_t sa = (sb0 + 1023u) & ~1023u;
    char* smem = smem_raw + (sa - sb0);
    const int tid = threadIdx.x, wid = tid >> 5, lane = tid & 31;
    const int mt0 = blockIdx.x * 64;
    const int f0  = blockIdx.y * 128;
    const int m0 = (wid & 1) * 32;
    const int n0 = (wid >> 1) * 32;

    char* Ah = smem;          char* Al = smem + 8192;
    char* Bh = smem + 16384;  char* Bl = smem + 32768;
    const uint32_t aAh = sa, aAl = sa + 8192, aBh = sa + 16384, aBl = sa + 32768;

    float w0 = lwp[0], w1 = lwp[1], w2 = lwp[2], w3 = lwp[3];
    float mx = fmaxf(fmaxf(w0, w1), fmaxf(w2, w3));
    float e0 = expf(w0-mx), e1 = expf(w1-mx), e2 = expf(w2-mx), e3 = expf(w3-mx);
    float inv = 1.0f / (e0+e1+e2+e3);
    float lw[4] = {e0*inv, e1*inv, e2*inv, e3*inv};
    const float* fs[4] = {fa, fb, fc, fd};

    const int aRow = lane & 15, aCol = (lane >> 4) * 8;
    const int bRow = (lane & 7) + ((lane >> 4) << 3);
    const int bCol = ((lane >> 3) & 1) * 8;

    float acc[2][4][4], oacc[2][4][4];
    #pragma unroll
    for (int i = 0; i < 2; i++)
        #pragma unroll
        for (int j = 0; j < 4; j++)
            #pragma unroll
            for (int q = 0; q < 4; q++) { acc[i][j][q] = 0.f; oacc[i][j][q] = 0.f; }

    for (int l = 0; l < 4; l++) {
        const float* fl = fs[l];
        for (int ch = 0; ch < 12; ch++) {
            const int kc0 = ch * 64;
            __syncthreads();
            for (int idx = tid; idx < 64 * 32; idx += 256) {
                int m = idx & 63, c2 = idx >> 6;
                int pix = mt0 + m, b = pix >> 10, n = pix & 1023;
                const float* ip = fl + ((size_t)b * CC + kc0 + 2 * c2) * N0 + n;
                float a0 = ip[0], a1 = ip[N0];
                __nv_bfloat16 h0, l0, h1, l1;
                split_bf16(a0, h0, l0); split_bf16(a1, h1, l1);
                uint32_t sw = SWZ(m * 128 + c2 * 4);
                *(uint32_t*)(Ah + sw) = pack2(h0, h1);
                *(uint32_t*)(Al + sw) = pack2(l0, l1);
            }
            for (int idx = tid; idx < 128 * 32; idx += 256) {
                int co = idx & 127, c2 = idx >> 7;
                size_t src = ((size_t)(l * 12 + ch) * 256 + f0 + co) * 32 + c2;
                uint32_t sw = SWZ(co * 128 + c2 * 4);
                *(uint32_t*)(Bh + sw) = g_pwH[src];
                *(uint32_t*)(Bl + sw) = g_pwL[src];
            }
            __syncthreads();
            #pragma unroll
            for (int ks = 0; ks < 4; ks++) {
                const int k0 = ks * 16;
                uint32_t ah[2][4], al[2][4], bh[2][4], bl[2][4];
                #pragma unroll
                for (int mf = 0; mf < 2; mf++) {
                    uint32_t off = SWZ((m0 + mf * 16 + aRow) * 128 + (k0 + aCol) * 2);
                    ldsm_x4(ah[mf], aAh + off);
                    ldsm_x4(al[mf], aAl + off);
                }
                #pragma unroll
                for (int nb = 0; nb < 2; nb++) {
                    uint32_t off = SWZ((n0 + nb * 16 + bRow) * 128 + (k0 + bCol) * 2);
                    ldsm_x4(bh[nb], aBh + off);
                    ldsm_x4(bl[nb], aBl + off);
                }
                #pragma unroll
                for (int mf = 0; mf < 2; mf++)
                    #pragma unroll
                    for (int nb = 0; nb < 2; nb++)
                        #pragma unroll
                        for (int oc = 0; oc < 2; oc++) {
                            float* d = acc[mf][nb * 2 + oc];
                            mma16816(d, ah[mf], &bh[nb][oc * 2]);
                            mma16816(d, ah[mf], &bl[nb][oc * 2]);
                            mma16816(d, al[mf], &bh[nb][oc * 2]);
                        }
            }
        }
        #pragma unroll
        for (int i = 0; i < 2; i++)
            #pragma unroll
            for (int j = 0; j < 4; j++)
                #pragma unroll
                for (int q = 0; q < 4; q++) {
                    float v = acc[i][j][q];
                    acc[i][j][q] = 0.f;
                    float g = 0.5f * v * (1.0f + erff(v * 0.70710678118654752f));
                    oacc[i][j][q] = fmaf(lw[l], g, oacc[i][j][q]);
                }
    }
    const int group = lane >> 2, tig = lane & 3;
    #pragma unroll
    for (int mf = 0; mf < 2; mf++)
        #pragma unroll
        for (int nb = 0; nb < 2; nb++)
            #pragma unroll
            for (int oc = 0; oc < 2; oc++) {
                const float* d = oacc[mf][nb * 2 + oc];
                int co = f0 + n0 + nb * 16 + oc * 8 + tig * 2;
                int m  = mt0 + m0 + mf * 16 + group;
                int b = m >> 10, n = m & 1023;
                size_t o0 = ((size_t)b * FF + co) * N0 + n;
                g_x0[o0]          = d[0];
                g_x0[o0 + N0]     = d[1];
                g_x0[o0 + 8]      = d[2];
                g_x0[o0 + N0 + 8] = d[3];
            }
}

// ---------------- depthwise + BN + residual ----------------
__global__ __launch_bounds__(256) void k_dw(const float* __restrict__ dww,
                                            const float* __restrict__ bn) {
    int idx = blockIdx.x * 256 + threadIdx.x;
    int w = idx & 31, h = (idx >> 5) & 31, f = (idx >> 10) & 255, b = idx >> 18;
    const float* pl = g_x0 + ((size_t)b*FF + f) * N0;
    float acc = 0.f;
    #pragma unroll
    for (int dy = 0; dy < 3; dy++) {
        int yy = h + dy - 1; if (yy < 0 || yy >= 32) continue;
        #pragma unroll
        for (int dx = 0; dx < 3; dx++) {
            int xx = w + dx - 1; if (xx < 0 || xx >= 32) continue;
            acc = fmaf(pl[yy*32+xx], dww[f*9+dy*3+dx], acc);
        }
    }
    float bnv = (acc - bn[512+f]) * bn[f] * rsqrtf(bn[768+f] + 1e-5f) + bn[256+f];
    g_x1[idx] = fmaxf(bnv + pl[h*32+w], 0.f);
}

// ---------------- offset conv 1x1 (256->32): 64px x 4 k-split groups ----------------
#define KO_SMEM (32768 + 33792)
__global__ __launch_bounds__(256) void k_off(const float* __restrict__ in,
    const float* __restrict__ ow, const float* __restrict__ ob,
    float* __restrict__ out, int HW) {
    extern __shared__ float ko[];
    float (*wT)[32] = (float(*)[32])ko;
    float (*sred)[64][33] = (float(*)[64][33])(ko + 8192);
    const int tid = threadIdx.x;
    for (int idx = tid; idx < 8192; idx += 256)
        wT[idx & 255][idx >> 8] = ow[(idx >> 8) * 256 + (idx & 255)];
    __syncthreads();
    const int px = tid & 63, grp = tid >> 6;
    const int hw = blockIdx.x * 64 + px, b = blockIdx.y;
    float acc[32];
    #pragma unroll
    for (int k = 0; k < 32; k++) acc[k] = 0.f;
    const float* ip = in + ((size_t)b * FF + grp * 64) * HW + hw;
    #pragma unroll 4
    for (int c = 0; c < 64; c++) {
        float v = ip[(size_t)c * HW];
        const float* wr = wT[grp * 64 + c];
        #pragma unroll
        for (int k8 = 0; k8 < 8; k8++) {
            float4 w4 = *(const float4*)&wr[k8 * 4];
            acc[k8*4+0]=fmaf(v,w4.x,acc[k8*4+0]); acc[k8*4+1]=fmaf(v,w4.y,acc[k8*4+1]);
            acc[k8*4+2]=fmaf(v,w4.z,acc[k8*4+2]); acc[k8*4+3]=fmaf(v,w4.w,acc[k8*4+3]);
        }
    }
    #pragma unroll
    for (int k = 0; k < 32; k++) sred[grp][px][k] = acc[k];
    __syncthreads();
    for (int idx = tid; idx < 2048; idx += 256) {
        int k = idx & 31, p = idx >> 5;
        float s = sred[0][p][k] + sred[1][p][k] + sred[2][p][k] + sred[3][p][k] + ob[k];
        out[((size_t)b * 32 + k) * HW + blockIdx.x * 64 + p] = s;
    }
}

// ---------------- DySample bilinear 2x -> packed bf16 hi/lo channel-pair planes ----------------
__global__ __launch_bounds__(256) void k_up(const float* __restrict__ in,
    const float* __restrict__ off, uint32_t* __restrict__ outH,
    uint32_t* __restrict__ outL, int H, int W) {
    int Ho = 2*H, Wo = 2*W;
    int idx = blockIdx.x * 256 + threadIdx.x;
    int X = idx % Wo; int t = idx / Wo;
    int Y = t % Ho;   t /= Ho;
    int c2 = t & 127, b = t >> 7;
    int cc0 = 2 * c2, g = cc0 >> 6;
    int h = Y >> 1, i = Y & 1, w = X >> 1, j = X & 1;
    int offc = (g << 2) + (i << 1) + j, HW = H * W;
    float ox = off[((size_t)b*32 + offc)*HW + h*W + w] * 0.25f + (j ? 0.25f : -0.25f);
    float oy = off[((size_t)b*32 + 16 + offc)*HW + h*W + w] * 0.25f + (i ? 0.25f : -0.25f);
    float px = fminf(fmaxf((float)w + ox, 0.f), (float)(W-1));
    float py = fminf(fmaxf((float)h + oy, 0.f), (float)(H-1));
    int x0 = (int)floorf(px), y0 = (int)floorf(py);
    float wx = px - x0, wy = py - y0;
    int x1 = min(x0+1, W-1), y1 = min(y0+1, H-1);
    const float* pl = in + ((size_t)b*FF + cc0)*HW;
    float w00 = (1.f-wy)*(1.f-wx), w01 = (1.f-wy)*wx, w10 = wy*(1.f-wx), w11 = wy*wx;
    float va = pl[y0*W+x0]*w00 + pl[y0*W+x1]*w01 + pl[y1*W+x0]*w10 + pl[y1*W+x1]*w11;
    const float* pl1 = pl + HW;
    float vb = pl1[y0*W+x0]*w00 + pl1[y0*W+x1]*w01 + pl1[y1*W+x0]*w10 + pl1[y1*W+x1]*w11;
    __nv_bfloat16 ha, la, hb, lb;
    split_bf16(va, ha, la); split_bf16(vb, hb, lb);
    size_t o = ((size_t)b * 128 + c2) * (Ho * Wo) + Y * Wo + X;
    outH[o] = pack2(ha, hb);
    outL[o] = pack2(la, lb);
}

// ---------------- HMMA implicit-GEMM conv: 32-ci chunks, SW64, 2 CTAs/SM ----------------
// per stage: Ah@0(8K) Al@8192(8K) Bh@16384(16K) Bl@32768(16K) = 49152
// FK=0: plain BN+ReLU epilogue.  FK=9: no main write; fused head 1x1 -> P planes.
#define STG 49152
#define CM_SMEM (2048 + 2*STG + 1024)
template<int FK>
__global__ __launch_bounds__(512) void k_conv_mma(
    const uint32_t* __restrict__ upH, const uint32_t* __restrict__ upL,
    const uint32_t* __restrict__ wH, const uint32_t* __restrict__ wL,
    const float* __restrict__ bn, float* __restrict__ out,
    const float* __restrict__ fw, float* __restrict__ fout, int W, int logW)
{
    extern __shared__ char smem_raw[];
    const uint32_t sb0 = smem_u32(smem_raw);
    const uint32_t sa = (sb0 + 1023u) & ~1023u;
    char* smem = smem_raw + (sa - sb0);
    const int tid = threadIdx.x, wid = tid >> 5, lane = tid & 31;
    const int HW = W * W;
    const int b = blockIdx.y;
    const int p0 = blockIdx.x * 128;

    float* sSc = (float*)(smem);
    float* sSh = (float*)(smem + 1024);
    if (tid < 256) {
        float sc = bn[tid] * rsqrtf(bn[768 + tid] + 1e-5f);
        sSc[tid] = sc;
        sSh[tid] = bn[256 + tid] - bn[512 + tid] * sc;
    }

    const uint32_t aStage = sa + 2048;
    const uint64_t zsrc = __cvta_generic_to_global(&g_zero4[0]);

    // fill 32-ci chunk ch (0..71) into stage s
    auto fill = [&](int ch, int s) {
        const int kpos = ch >> 3;
        const int cb2 = (ch & 7) * 16;               // global c2 base (16 pairs)
        const int ky = kpos / 3 - 1, kx = kpos % 3 - 1;
        const uint32_t stg = aStage + s * STG;
        // A: 128 px x 16 c2, 4B each (H and L planes)
        #pragma unroll
        for (int r = 0; r < 4; r++) {
            int idx = tid + r * 512;
            int m = idx & 127, c2 = idx >> 7;        // c2 in [0,16)
            int pix = p0 + m;
            int y = (pix >> logW) + ky, x = (pix & (W - 1)) + kx;
            bool ok = (y >= 0 && y < W && x >= 0 && x < W);
            uint64_t srcH = zsrc, srcL = zsrc;
            if (ok) {
                size_t e = ((size_t)b * 128 + cb2 + c2) * HW + y * W + x;
                srcH = __cvta_generic_to_global(&upH[e]);
                srcL = __cvta_generic_to_global(&upL[e]);
            }
            uint32_t sw = SWZ64(m * 64 + c2 * 4);
            CP_A4(stg + sw, srcH);
            CP_A4(stg + 8192 + sw, srcL);
        }
        // B: 256 co x 16 c2, 16B quads (H and L planes)
        #pragma unroll
        for (int r = 0; r < 2; r++) {
            int q = tid + r * 512;                   // 1024 quads
            int co = q >> 2, c2q = q & 3;
            size_t src = ((size_t)(ch >> 1) * 256 + co) * 32 + (ch & 1) * 16 + c2q * 4;
            uint32_t sw = SWZ64(co * 64 + c2q * 16);
            CP_A16(stg + 16384 + sw, __cvta_generic_to_global(&wH[src]));
            CP_A16(stg + 32768 + sw, __cvta_generic_to_global(&wL[src]));
        }
    };

    const int m0 = (wid & 3) * 32;
    const int n0 = (wid >> 2) * 64;
    const int aRow = lane & 15, aCol = (lane >> 4) * 8;
    const int bRow = (lane & 7) + ((lane >> 4) << 3);
    const int bCol = ((lane >> 3) & 1) * 8;

    float acc[2][8][4];
    #pragma unroll
    for (int i = 0; i < 2; i++)
        #pragma unroll
        for (int j = 0; j < 8; j++)
            #pragma unroll
            for (int q = 0; q < 4; q++) acc[i][j][q] = 0.f;

    fill(0, 0); CP_COMMIT();

    for (int ch = 0; ch < 72; ch++) {
        if (ch < 71) { fill(ch + 1, (ch + 1) & 1); CP_COMMIT(); CP_WAIT1(); }
        else         { CP_WAIT0(); }
        __syncthreads();
        const uint32_t stg = aStage + (ch & 1) * STG;
        const uint32_t aAh = stg, aAl = stg + 8192, aBh = stg + 16384, aBl = stg + 32768;
        #pragma unroll
        for (int ks = 0; ks < 2; ks++) {
            const int k0 = ks * 16;
            uint32_t ah[2][4], al[2][4], bh[4][4], bl[4][4];
            #pragma unroll
            for (int mf = 0; mf < 2; mf++) {
                uint32_t off = SWZ64((m0 + mf * 16 + aRow) * 64 + (k0 + aCol) * 2);
                ldsm_x4(ah[mf], aAh + off);
                ldsm_x4(al[mf], aAl + off);
            }
            #pragma unroll
            for (int nb = 0; nb < 4; nb++) {
                uint32_t off = SWZ64((n0 + nb * 16 + bRow) * 64 + (k0 + bCol) * 2);
                ldsm_x4(bh[nb], aBh + off);
                ldsm_x4(bl[nb], aBl + off);
            }
            #pragma unroll
            for (int mf = 0; mf < 2; mf++)
                #pragma unroll
                for (int nb = 0; nb < 4; nb++)
                    #pragma unroll
                    for (int oc = 0; oc < 2; oc++) {
                        float* d = acc[mf][nb * 2 + oc];
                        mma16816(d, ah[mf], &bh[nb][oc * 2]);
                        mma16816(d, ah[mf], &bl[nb][oc * 2]);
                        mma16816(d, al[mf], &bh[nb][oc * 2]);
                    }
        }
        __syncthreads();
    }

    const int group = lane >> 2, tig = lane & 3;
    if constexpr (FK == 0) {
        #pragma unroll
        for (int mf = 0; mf < 2; mf++)
            #pragma unroll
            for (int nb = 0; nb < 4; nb++)
                #pragma unroll
                for (int oc = 0; oc < 2; oc++) {
                    const float* d = acc[mf][nb * 2 + oc];
                    int co = n0 + nb * 16 + oc * 8 + tig * 2;
                    int m  = m0 + mf * 16 + group;
                    float s0 = sSc[co], h0 = sSh[co], s1 = sSc[co+1], h1 = sSh[co+1];
                    size_t o0 = ((size_t)b * FF + co) * HW + p0 + m;
                    out[o0]           = fmaxf(fmaf(d[0], s0, h0), 0.f);
                    out[o0 + HW]      = fmaxf(fmaf(d[1], s1, h1), 0.f);
                    out[o0 + 8]       = fmaxf(fmaf(d[2], s0, h0), 0.f);
                    out[o0 + HW + 8]  = fmaxf(fmaf(d[3], s1, h1), 0.f);
                }
    } else {
        constexpr int FKR = FK ? FK : 1;
        float* sW = (float*)(smem + 2048);            // [co][FK]
        float* sO = sW + 256 * FKR;                   // [FK][128]
        for (int i = tid; i < 256 * FKR; i += 512) sW[i] = fw[i];
        for (int i = tid; i < FKR * 128; i += 512) sO[i] = 0.f;
        __syncthreads();
        #pragma unroll
        for (int mf = 0; mf < 2; mf++)
            #pragma unroll
            for (int hi = 0; hi < 2; hi++) {
                const int mloc = m0 + mf * 16 + group + hi * 8;
                float pk[FKR];
                #pragma unroll
                for (int k = 0; k < FKR; k++) pk[k] = 0.f;
                #pragma unroll
                for (int nb = 0; nb < 4; nb++)
                    #pragma unroll
                    for (int oc = 0; oc < 2; oc++) {
                        const float* d = acc[mf][nb * 2 + oc];
                        int co = n0 + nb * 16 + oc * 8 + tig * 2;
                        float v0 = fmaxf(fmaf(d[hi*2+0], sSc[co],   sSh[co]),   0.f);
                        float v1 = fmaxf(fmaf(d[hi*2+1], sSc[co+1], sSh[co+1]), 0.f);
                        #pragma unroll
                        for (int k = 0; k < FKR; k++)
                            pk[k] = fmaf(v0, sW[co * FKR + k],
                                    fmaf(v1, sW[(co + 1) * FKR + k], pk[k]));
                    }
                #pragma unroll
                for (int k = 0; k < FKR; k++) {
                    pk[k] += __shfl_xor_sync(0xFFFFFFFF, pk[k], 1);
                    pk[k] += __shfl_xor_sync(0xFFFFFFFF, pk[k], 2);
                }
                if (tig == 0)
                    #pragma unroll
                    for (int k = 0; k < FKR; k++)
                        atomicAdd(&sO[k * 128 + mloc], pk[k]);
            }
        __syncthreads();
        for (int i = tid; i < FKR * 128; i += 512) {
            int k = i >> 7, m = i & 127;
            fout[((size_t)b * FKR + k) * HW + p0 + m] = sO[i];
        }
    }
}

// ---------------- head stage 2: 9-tap shift-add + bias ----------------
__global__ __launch_bounds__(256) void k_head2(const float* __restrict__ bias,
                                               float* __restrict__ out) {
    int idx = blockIdx.x * 256 + threadIdx.x;       // BB*16384
    int x = idx & 127, y = (idx >> 7) & 127, b = idx >> 14;
    float s = bias[0];
    #pragma unroll
    for (int ky = 0; ky < 3; ky++) {
        int yy = y + ky - 1;
        if (yy < 0 || yy >= 128) continue;
        #pragma unroll
        for (int kx = 0; kx < 3; kx++) {
            int xx = x + kx - 1;
            if (xx < 0 || xx >= 128) continue;
            s += g_P[(((size_t)b * 9 + ky * 3 + kx) << 14) + yy * 128 + xx];
        }
    }
    out[idx] = s;
}

// ---------------- launch ----------------
extern "C" void kernel_launch(void* const* d_in, const int* in_sizes, int n_in,
                              void* d_out, int out_size)
{
    const float* f1  = (const float*)d_in[0];
    const float* f2  = (const float*)d_in[1];
    const float* f3  = (const float*)d_in[2];
    const float* f4  = (const float*)d_in[3];
    const float* pw  = (const float*)d_in[4];
    const float* lwv = (const float*)d_in[5];
    const float* dww = (const float*)d_in[6];
    const float* bne = (const float*)d_in[7];
    const float* ow1 = (const float*)d_in[8];
    const float* ob1 = (const float*)d_in[9];
    const float* cw1 = (const float*)d_in[10];
    const float* bn1 = (const float*)d_in[11];
    const float* ow2 = (const float*)d_in[12];
    const float* ob2 = (const float*)d_in[13];
    const float* cw2 = (const float*)d_in[14];
    const float* bn2 = (const float*)d_in[15];
    const float* hw  = (const float*)d_in[16];
    const float* hb  = (const float*)d_in[17];
    float* out = (float*)d_out;

    float *p_x1, *p_off1, *p_c1, *p_off2, *p_P;
    uint32_t *p_u1H, *p_u1L, *p_u2H, *p_u2L, *p_w1H, *p_w1L, *p_w2H, *p_w2L;
    cudaGetSymbolAddress((void**)&p_x1,  g_x1);
    cudaGetSymbolAddress((void**)&p_off1, g_off1);
    cudaGetSymbolAddress((void**)&p_c1,  g_c1);
    cudaGetSymbolAddress((void**)&p_off2, g_off2);
    cudaGetSymbolAddress((void**)&p_P,   g_P);
    cudaGetSymbolAddress((void**)&p_u1H, g_up1H);
    cudaGetSymbolAddress((void**)&p_u1L, g_up1L);
    cudaGetSymbolAddress((void**)&p_u2H, g_up2H);
    cudaGetSymbolAddress((void**)&p_u2L, g_up2L);
    cudaGetSymbolAddress((void**)&p_w1H, g_w1H);
    cudaGetSymbolAddress((void**)&p_w1L, g_w1L);
    cudaGetSymbolAddress((void**)&p_w2H, g_w2H);
    cudaGetSymbolAddress((void**)&p_w2L, g_w2L);

    cudaFuncSetAttribute(k_conv_mma<0>, cudaFuncAttributeMaxDynamicSharedMemorySize, CM_SMEM);
    cudaFuncSetAttribute(k_conv_mma<9>, cudaFuncAttributeMaxDynamicSharedMemorySize, CM_SMEM);
    cudaFuncSetAttribute(k_fusion_mma,  cudaFuncAttributeMaxDynamicSharedMemorySize, FM_SMEM);
    cudaFuncSetAttribute(k_off,         cudaFuncAttributeMaxDynamicSharedMemorySize, KO_SMEM);

    k_prep_w<<<(2*294912)/256, 256>>>(cw1, cw2);
    k_prep_pw<<<393216/256, 256>>>(pw);
    k_fusion_mma<<<dim3(64, 2), 256, FM_SMEM>>>(f1, f2, f3, f4, lwv);
    k_dw<<<(BB*FF*N0)/256, 256>>>(dww, bne);
    k_off<<<dim3(N0/64, BB), 256, KO_SMEM>>>(p_x1, ow1, ob1, p_off1, N0);
    k_up<<<(BB*128*4*N0)/256, 256>>>(p_x1, p_off1, p_u1H, p_u1L, 32, 32);
    k_conv_mma<0><<<dim3(4*N0/128, BB), 512, CM_SMEM>>>(
        p_u1H, p_u1L, p_w1H, p_w1L, bn1, p_c1, nullptr, nullptr, 64, 6);
    k_off<<<dim3(4*N0/64, BB), 256, KO_SMEM>>>(p_c1, ow2, ob2, p_off2, 4*N0);
    k_up<<<(BB*128*16*N0)/256, 256>>>(p_c1, p_off2, p_u2H, p_u2L, 64, 64);
    k_conv_mma<9><<<dim3(16*N0/128, BB), 512, CM_SMEM>>>(
        p_u2H, p_u2L, p_w2H, p_w2L, bn2, nullptr, hw, p_P, 128, 7);
    k_head2<<<(BB*16384)/256, 256>>>(hb, out);
}

// round 16
// speedup vs baseline: 1.2173x; 1.2173x over previous
#include <cuda_runtime.h>
#include <cuda_bf16.h>
#include <cuda_fp16.h>
#include <cstdint>
#include <math.h>

#define BB 4
#define CC 768
#define FF 256
#define N0 1024

// ---------------- scratch ----------------
__device__ float g_x0 [BB*FF*N0];
__device__ float g_x1 [BB*FF*N0];
__device__ float g_off1[BB*32*N0];
__device__ float g_off2[BB*32*4*N0];
__device__ float g_c1 [BB*FF*4*N0];
__device__ float g_P  [BB*9*16*N0];            // head partial planes
__device__ uint32_t g_up1H[BB*128*4*N0];       // fp16x2 hi planes
__device__ uint32_t g_up1L[BB*128*4*N0];       // fp16x2 lo planes
__device__ uint32_t g_up2H[BB*128*16*N0];
__device__ uint32_t g_up2L[BB*128*16*N0];
__device__ uint32_t g_w1H[294912];             // fp16x2 weights (single plane)
__device__ uint32_t g_w2H[294912];
__device__ uint32_t g_pwH[393216], g_pwL[393216];  // fusion bf16 hi/lo
__device__ float g_zero4[4] = {0.f, 0.f, 0.f, 0.f};

// ---------------- helpers ----------------
__device__ __forceinline__ uint32_t smem_u32(const void* p) {
    uint32_t a; asm("{ .reg .u64 t; cvta.to.shared.u64 t, %1; cvt.u32.u64 %0, t; }"
                    : "=r"(a) : "l"(p)); return a;
}
#define SWZ(x) ((uint32_t)(x) ^ ((((uint32_t)(x)) >> 3) & 0x70u))

__device__ __forceinline__ void ldsm_x4(uint32_t (&r)[4], uint32_t addr) {
    asm volatile("ldmatrix.sync.aligned.m8n8.x4.shared.b16 {%0,%1,%2,%3}, [%4];"
        : "=r"(r[0]), "=r"(r[1]), "=r"(r[2]), "=r"(r[3]) : "r"(addr));
}
// bf16 mma (fusion)
__device__ __forceinline__ void mma_bf(float* d, const uint32_t* a, const uint32_t* b) {
    asm volatile("mma.sync.aligned.m16n8k16.row.col.f32.bf16.bf16.f32 "
        "{%0,%1,%2,%3}, {%4,%5,%6,%7}, {%8,%9}, {%0,%1,%2,%3};"
        : "+f"(d[0]), "+f"(d[1]), "+f"(d[2]), "+f"(d[3])
        : "r"(a[0]), "r"(a[1]), "r"(a[2]), "r"(a[3]), "r"(b[0]), "r"(b[1]));
}
// fp16 mma (convs)
__device__ __forceinline__ void mma_fp(float* d, const uint32_t* a, const uint32_t* b) {
    asm volatile("mma.sync.aligned.m16n8k16.row.col.f32.f16.f16.f32 "
        "{%0,%1,%2,%3}, {%4,%5,%6,%7}, {%8,%9}, {%0,%1,%2,%3};"
        : "+f"(d[0]), "+f"(d[1]), "+f"(d[2]), "+f"(d[3])
        : "r"(a[0]), "r"(a[1]), "r"(a[2]), "r"(a[3]), "r"(b[0]), "r"(b[1]));
}
__device__ __forceinline__ void split_bf16(float v, __nv_bfloat16& h, __nv_bfloat16& l) {
    h = __float2bfloat16(v);
    l = __float2bfloat16(v - __bfloat162float(h));
}
__device__ __forceinline__ uint32_t pack2bf(__nv_bfloat16 a, __nv_bfloat16 b) {
    __nv_bfloat162 t = __halves2bfloat162(a, b);
    return *(uint32_t*)&t;
}
__device__ __forceinline__ void split_fp16(float v, __half& h, __half& l) {
    h = __float2half_rn(v);
    l = __float2half_rn(v - __half2float(h));
}
__device__ __forceinline__ uint32_t pack2h(__half a, __half b) {
    __half2 t = __halves2half2(a, b);
    return *(uint32_t*)&t;
}
#define CP_A4(dst, src)  asm volatile("cp.async.ca.shared.global [%0], [%1], 4;"  :: "r"(dst), "l"(src))
#define CP_A16(dst, src) asm volatile("cp.async.cg.shared.global [%0], [%1], 16;" :: "r"(dst), "l"(src))
#define CP_COMMIT() asm volatile("cp.async.commit_group;" ::: "memory")
#define CP_WAIT0()  asm volatile("cp.async.wait_group 0;" ::: "memory")
#define CP_WAIT1()  asm volatile("cp.async.wait_group 1;" ::: "memory")

// ---------------- conv weight pre-pack: OIHW -> [ch36][co][c2 32] fp16x2 ----------------
__global__ __launch_bounds__(256) void k_prep_w(const float* __restrict__ w1,
                                                const float* __restrict__ w2) {
    int idx = blockIdx.x * 256 + threadIdx.x;
    int which = idx >= 294912;
    int t = which ? idx - 294912 : idx;
    int c2 = t & 31, co = (t >> 5) & 255, ch = t >> 13;
    int kpos = ch >> 2, ci = (ch & 3) * 64 + 2 * c2;
    const float* w = which ? w2 : w1;
    float v0 = w[(co * 256 + ci) * 9 + kpos];
    float v1 = w[(co * 256 + ci + 1) * 9 + kpos];
    (which ? g_w2H : g_w1H)[t] = pack2h(__float2half_rn(v0), __float2half_rn(v1));
}

// ---------------- fusion weight pre-pack (bf16 hi/lo) ----------------
__global__ __launch_bounds__(256) void k_prep_pw(const float* __restrict__ pw) {
    int t = blockIdx.x * 256 + threadIdx.x;
    int c2 = t & 31, co = (t >> 5) & 255, r = t >> 13;
    int l = r / 12, ch = r - l * 12;
    int c = ch * 64 + 2 * c2;
    float v0 = pw[((size_t)l * CC + c) * FF + co];
    float v1 = pw[((size_t)l * CC + c + 1) * FF + co];
    __nv_bfloat16 h0, l0, h1, l1;
    split_bf16(v0, h0, l0); split_bf16(v1, h1, l1);
    g_pwH[t] = pack2bf(h0, h1);
    g_pwL[t] = pack2bf(l0, l1);
}

// ---------------- fusion GEMM: HMMA bf16 3-term, GELU + weighted layer sum ----------------
#define FM_SMEM (49152 + 1024)
__global__ __launch_bounds__(256) void k_fusion_mma(
    const float* __restrict__ fa, const float* __restrict__ fb,
    const float* __restrict__ fc, const float* __restrict__ fd,
    const float* __restrict__ lwp)
{
    extern __shared__ char smem_raw[];
    const uint32_t sb0 = smem_u32(smem_raw);
    const uint32_t sa = (sb0 + 1023u) & ~1023u;
    char* smem = smem_raw + (sa - sb0);
    const int tid = threadIdx.x, wid = tid >> 5, lane = tid & 31;
    const int mt0 = blockIdx.x * 64;
    const int f0  = blockIdx.y * 128;
    const int m0 = (wid & 1) * 32;
    const int n0 = (wid >> 1) * 32;

    char* Ah = smem;          char* Al = smem + 8192;
    char* Bh = smem + 16384;  char* Bl = smem + 32768;
    const uint32_t aAh = sa, aAl = sa + 8192, aBh = sa + 16384, aBl = sa + 32768;

    float w0 = lwp[0], w1 = lwp[1], w2 = lwp[2], w3 = lwp[3];
    float mx = fmaxf(fmaxf(w0, w1), fmaxf(w2, w3));
    float e0 = expf(w0-mx), e1 = expf(w1-mx), e2 = expf(w2-mx), e3 = expf(w3-mx);
    float inv = 1.0f / (e0+e1+e2+e3);
    float lw[4] = {e0*inv, e1*inv, e2*inv, e3*inv};
    const float* fs[4] = {fa, fb, fc, fd};

    const int aRow = lane & 15, aCol = (lane >> 4) * 8;
    const int bRow = (lane & 7) + ((lane >> 4) << 3);
    const int bCol = ((lane >> 3) & 1) * 8;

    float acc[2][4][4], oacc[2][4][4];
    #pragma unroll
    for (int i = 0; i < 2; i++)
        #pragma unroll
        for (int j = 0; j < 4; j++)
            #pragma unroll
            for (int q = 0; q < 4; q++) { acc[i][j][q] = 0.f; oacc[i][j][q] = 0.f; }

    for (int l = 0; l < 4; l++) {
        const float* fl = fs[l];
        for (int ch = 0; ch < 12; ch++) {
            const int kc0 = ch * 64;
            __syncthreads();
            for (int idx = tid; idx < 64 * 32; idx += 256) {
                int m = idx & 63, c2 = idx >> 6;
                int pix = mt0 + m, b = pix >> 10, n = pix & 1023;
                const float* ip = fl + ((size_t)b * CC + kc0 + 2 * c2) * N0 + n;
                float a0 = ip[0], a1 = ip[N0];
                __nv_bfloat16 h0, l0, h1, l1;
                split_bf16(a0, h0, l0); split_bf16(a1, h1, l1);
                uint32_t sw = SWZ(m * 128 + c2 * 4);
                *(uint32_t*)(Ah + sw) = pack2bf(h0, h1);
                *(uint32_t*)(Al + sw) = pack2bf(l0, l1);
            }
            for (int idx = tid; idx < 128 * 32; idx += 256) {
                int co = idx & 127, c2 = idx >> 7;
                size_t src = ((size_t)(l * 12 + ch) * 256 + f0 + co) * 32 + c2;
                uint32_t sw = SWZ(co * 128 + c2 * 4);
                *(uint32_t*)(Bh + sw) = g_pwH[src];
                *(uint32_t*)(Bl + sw) = g_pwL[src];
            }
            __syncthreads();
            #pragma unroll
            for (int ks = 0; ks < 4; ks++) {
                const int k0 = ks * 16;
                uint32_t ah[2][4], al[2][4], bh[2][4], bl[2][4];
                #pragma unroll
                for (int mf = 0; mf < 2; mf++) {
                    uint32_t off = SWZ((m0 + mf * 16 + aRow) * 128 + (k0 + aCol) * 2);
                    ldsm_x4(ah[mf], aAh + off);
                    ldsm_x4(al[mf], aAl + off);
                }
                #pragma unroll
                for (int nb = 0; nb < 2; nb++) {
                    uint32_t off = SWZ((n0 + nb * 16 + bRow) * 128 + (k0 + bCol) * 2);
                    ldsm_x4(bh[nb], aBh + off);
                    ldsm_x4(bl[nb], aBl + off);
                }
                #pragma unroll
                for (int mf = 0; mf < 2; mf++)
                    #pragma unroll
                    for (int nb = 0; nb < 2; nb++)
                        #pragma unroll
                        for (int oc = 0; oc < 2; oc++) {
                            float* d = acc[mf][nb * 2 + oc];
                            mma_bf(d, ah[mf], &bh[nb][oc * 2]);
                            mma_bf(d, ah[mf], &bl[nb][oc * 2]);
                            mma_bf(d, al[mf], &bh[nb][oc * 2]);
                        }
            }
        }
        #pragma unroll
        for (int i = 0; i < 2; i++)
            #pragma unroll
            for (int j = 0; j < 4; j++)
                #pragma unroll
                for (int q = 0; q < 4; q++) {
                    float v = acc[i][j][q];
                    acc[i][j][q] = 0.f;
                    float g = 0.5f * v * (1.0f + erff(v * 0.70710678118654752f));
                    oacc[i][j][q] = fmaf(lw[l], g, oacc[i][j][q]);
                }
    }
    const int group = lane >> 2, tig = lane & 3;
    #pragma unroll
    for (int mf = 0; mf < 2; mf++)
        #pragma unroll
        for (int nb = 0; nb < 2; nb++)
            #pragma unroll
            for (int oc = 0; oc < 2; oc++) {
                const float* d = oacc[mf][nb * 2 + oc];
                int co = f0 + n0 + nb * 16 + oc * 8 + tig * 2;
                int m  = mt0 + m0 + mf * 16 + group;
                int b = m >> 10, n = m & 1023;
                size_t o0 = ((size_t)b * FF + co) * N0 + n;
                g_x0[o0]          = d[0];
                g_x0[o0 + N0]     = d[1];
                g_x0[o0 + 8]      = d[2];
                g_x0[o0 + N0 + 8] = d[3];
            }
}

// ---------------- depthwise + BN + residual ----------------
__global__ __launch_bounds__(256) void k_dw(const float* __restrict__ dww,
                                            const float* __restrict__ bn) {
    int idx = blockIdx.x * 256 + threadIdx.x;
    int w = idx & 31, h = (idx >> 5) & 31, f = (idx >> 10) & 255, b = idx >> 18;
    const float* pl = g_x0 + ((size_t)b*FF + f) * N0;
    float acc = 0.f;
    #pragma unroll
    for (int dy = 0; dy < 3; dy++) {
        int yy = h + dy - 1; if (yy < 0 || yy >= 32) continue;
        #pragma unroll
        for (int dx = 0; dx < 3; dx++) {
            int xx = w + dx - 1; if (xx < 0 || xx >= 32) continue;
            acc = fmaf(pl[yy*32+xx], dww[f*9+dy*3+dx], acc);
        }
    }
    float bnv = (acc - bn[512+f]) * bn[f] * rsqrtf(bn[768+f] + 1e-5f) + bn[256+f];
    g_x1[idx] = fmaxf(bnv + pl[h*32+w], 0.f);
}

// ---------------- offset conv 1x1 (256->32): 64px x 4 k-split groups ----------------
#define KO_SMEM (32768 + 33792)
__global__ __launch_bounds__(256) void k_off(const float* __restrict__ in,
    const float* __restrict__ ow, const float* __restrict__ ob,
    float* __restrict__ out, int HW) {
    extern __shared__ float ko[];
    float (*wT)[32] = (float(*)[32])ko;
    float (*sred)[64][33] = (float(*)[64][33])(ko + 8192);
    const int tid = threadIdx.x;
    for (int idx = tid; idx < 8192; idx += 256)
        wT[idx & 255][idx >> 8] = ow[(idx >> 8) * 256 + (idx & 255)];
    __syncthreads();
    const int px = tid & 63, grp = tid >> 6;
    const int hw = blockIdx.x * 64 + px, b = blockIdx.y;
    float acc[32];
    #pragma unroll
    for (int k = 0; k < 32; k++) acc[k] = 0.f;
    const float* ip = in + ((size_t)b * FF + grp * 64) * HW + hw;
    #pragma unroll 4
    for (int c = 0; c < 64; c++) {
        float v = ip[(size_t)c * HW];
        const float* wr = wT[grp * 64 + c];
        #pragma unroll
        for (int k8 = 0; k8 < 8; k8++) {
            float4 w4 = *(const float4*)&wr[k8 * 4];
            acc[k8*4+0]=fmaf(v,w4.x,acc[k8*4+0]); acc[k8*4+1]=fmaf(v,w4.y,acc[k8*4+1]);
            acc[k8*4+2]=fmaf(v,w4.z,acc[k8*4+2]); acc[k8*4+3]=fmaf(v,w4.w,acc[k8*4+3]);
        }
    }
    #pragma unroll
    for (int k = 0; k < 32; k++) sred[grp][px][k] = acc[k];
    __syncthreads();
    for (int idx = tid; idx < 2048; idx += 256) {
        int k = idx & 31, p = idx >> 5;
        float s = sred[0][p][k] + sred[1][p][k] + sred[2][p][k] + sred[3][p][k] + ob[k];
        out[((size_t)b * 32 + k) * HW + blockIdx.x * 64 + p] = s;
    }
}

// ---------------- DySample bilinear 2x -> packed fp16 hi/lo channel-pair planes ----------------
__global__ __launch_bounds__(256) void k_up(const float* __restrict__ in,
    const float* __restrict__ off, uint32_t* __restrict__ outH,
    uint32_t* __restrict__ outL, int H, int W) {
    int Ho = 2*H, Wo = 2*W;
    int idx = blockIdx.x * 256 + threadIdx.x;
    int X = idx % Wo; int t = idx / Wo;
    int Y = t % Ho;   t /= Ho;
    int c2 = t & 127, b = t >> 7;
    int cc0 = 2 * c2, g = cc0 >> 6;
    int h = Y >> 1, i = Y & 1, w = X >> 1, j = X & 1;
    int offc = (g << 2) + (i << 1) + j, HW = H * W;
    float ox = off[((size_t)b*32 + offc)*HW + h*W + w] * 0.25f + (j ? 0.25f : -0.25f);
    float oy = off[((size_t)b*32 + 16 + offc)*HW + h*W + w] * 0.25f + (i ? 0.25f : -0.25f);
    float px = fminf(fmaxf((float)w + ox, 0.f), (float)(W-1));
    float py = fminf(fmaxf((float)h + oy, 0.f), (float)(H-1));
    int x0 = (int)floorf(px), y0 = (int)floorf(py);
    float wx = px - x0, wy = py - y0;
    int x1 = min(x0+1, W-1), y1 = min(y0+1, H-1);
    const float* pl = in + ((size_t)b*FF + cc0)*HW;
    float w00 = (1.f-wy)*(1.f-wx), w01 = (1.f-wy)*wx, w10 = wy*(1.f-wx), w11 = wy*wx;
    float va = pl[y0*W+x0]*w00 + pl[y0*W+x1]*w01 + pl[y1*W+x0]*w10 + pl[y1*W+x1]*w11;
    const float* pl1 = pl + HW;
    float vb = pl1[y0*W+x0]*w00 + pl1[y0*W+x1]*w01 + pl1[y1*W+x0]*w10 + pl1[y1*W+x1]*w11;
    __half ha, la, hb, lb;
    split_fp16(va, ha, la); split_fp16(vb, hb, lb);
    size_t o = ((size_t)b * 128 + c2) * (Ho * Wo) + Y * Wo + X;
    outH[o] = pack2h(ha, hb);
    outL[o] = pack2h(la, lb);
}

// ---------------- HMMA fp16 2-term implicit-GEMM conv, cp.async double-buffered ----------------
// per stage: Ah@0(16K) Al@16384(16K) Bh@32768(32K) = 65536
// FK=0: plain BN+ReLU epilogue.  FK=9: no main write; fused head 1x1 -> P planes.
#define STG 65536
#define CM_SMEM (2048 + 2*STG + 1024)
template<int FK>
__global__ __launch_bounds__(512) void k_conv_mma(
    const uint32_t* __restrict__ upH, const uint32_t* __restrict__ upL,
    const uint32_t* __restrict__ wH,
    const float* __restrict__ bn, float* __restrict__ out,
    const float* __restrict__ fw, float* __restrict__ fout, int W, int logW)
{
    extern __shared__ char smem_raw[];
    const uint32_t sb0 = smem_u32(smem_raw);
    const uint32_t sa = (sb0 + 1023u) & ~1023u;
    char* smem = smem_raw + (sa - sb0);
    const int tid = threadIdx.x, wid = tid >> 5, lane = tid & 31;
    const int HW = W * W;
    const int b = blockIdx.y;
    const int p0 = blockIdx.x * 128;

    float* sSc = (float*)(smem);
    float* sSh = (float*)(smem + 1024);
    if (tid < 256) {
        float sc = bn[tid] * rsqrtf(bn[768 + tid] + 1e-5f);
        sSc[tid] = sc;
        sSh[tid] = bn[256 + tid] - bn[512 + tid] * sc;
    }

    const uint32_t aStage = sa + 2048;
    const uint64_t zsrc = __cvta_generic_to_global(&g_zero4[0]);

    auto fill = [&](int ch, int s) {
        const int kpos = ch >> 2;
        const int cb2 = (ch & 3) * 32;
        const int ky = kpos / 3 - 1, kx = kpos % 3 - 1;
        const uint32_t stg = aStage + s * STG;
        // A: 128 px x 32 c2, hi+lo planes
        #pragma unroll
        for (int r = 0; r < 8; r++) {
            int idx = tid + r * 512;
            int m = idx & 127, c2 = idx >> 7;
            int pix = p0 + m;
            int y = (pix >> logW) + ky, x = (pix & (W - 1)) + kx;
            bool ok = (y >= 0 && y < W && x >= 0 && x < W);
            uint64_t srcH = zsrc, srcL = zsrc;
            if (ok) {
                size_t e = ((size_t)b * 128 + cb2 + c2) * HW + y * W + x;
                srcH = __cvta_generic_to_global(&upH[e]);
                srcL = __cvta_generic_to_global(&upL[e]);
            }
            uint32_t sw = SWZ(m * 128 + c2 * 4);
            CP_A4(stg + sw, srcH);
            CP_A4(stg + 16384 + sw, srcL);
        }
        // B: 256 co x 32 c2, single fp16 plane, 16B quads
        #pragma unroll
        for (int r = 0; r < 4; r++) {
            int q = tid + r * 512;                   // 2048 quads
            int co = q >> 3, c2q = q & 7;
            size_t src = ((size_t)ch * 256 + co) * 32 + c2q * 4;
            uint32_t sw = SWZ(co * 128 + c2q * 16);
            CP_A16(stg + 32768 + sw, __cvta_generic_to_global(&wH[src]));
        }
    };

    const int m0 = (wid & 3) * 32;
    const int n0 = (wid >> 2) * 64;
    const int aRow = lane & 15, aCol = (lane >> 4) * 8;
    const int bRow = (lane & 7) + ((lane >> 4) << 3);
    const int bCol = ((lane >> 3) & 1) * 8;

    float acc[2][8][4];
    #pragma unroll
    for (int i = 0; i < 2; i++)
        #pragma unroll
        for (int j = 0; j < 8; j++)
            #pragma unroll
            for (int q = 0; q < 4; q++) acc[i][j][q] = 0.f;

    fill(0, 0); CP_COMMIT();

    for (int ch = 0; ch < 36; ch++) {
        if (ch < 35) { fill(ch + 1, (ch + 1) & 1); CP_COMMIT(); CP_WAIT1(); }
        else         { CP_WAIT0(); }
        __syncthreads();
        const uint32_t stg = aStage + (ch & 1) * STG;
        const uint32_t aAh = stg, aAl = stg + 16384, aBh = stg + 32768;
        #pragma unroll
        for (int ks = 0; ks < 4; ks++) {
            const int k0 = ks * 16;
            uint32_t ah[2][4], al[2][4], bh[4][4];
            #pragma unroll
            for (int mf = 0; mf < 2; mf++) {
                uint32_t off = SWZ((m0 + mf * 16 + aRow) * 128 + (k0 + aCol) * 2);
                ldsm_x4(ah[mf], aAh + off);
                ldsm_x4(al[mf], aAl + off);
            }
            #pragma unroll
            for (int nb = 0; nb < 4; nb++) {
                uint32_t off = SWZ((n0 + nb * 16 + bRow) * 128 + (k0 + bCol) * 2);
                ldsm_x4(bh[nb], aBh + off);
            }
            #pragma unroll
            for (int mf = 0; mf < 2; mf++)
                #pragma unroll
                for (int nb = 0; nb < 4; nb++)
                    #pragma unroll
                    for (int oc = 0; oc < 2; oc++) {
                        float* d = acc[mf][nb * 2 + oc];
                        mma_fp(d, ah[mf], &bh[nb][oc * 2]);
                        mma_fp(d, al[mf], &bh[nb][oc * 2]);
                    }
        }
        __syncthreads();
    }

    const int group = lane >> 2, tig = lane & 3;
    if constexpr (FK == 0) {
        #pragma unroll
        for (int mf = 0; mf < 2; mf++)
            #pragma unroll
            for (int nb = 0; nb < 4; nb++)
                #pragma unroll
                for (int oc = 0; oc < 2; oc++) {
                    const float* d = acc[mf][nb * 2 + oc];
                    int co = n0 + nb * 16 + oc * 8 + tig * 2;
                    int m  = m0 + mf * 16 + group;
                    float s0 = sSc[co], h0 = sSh[co], s1 = sSc[co+1], h1 = sSh[co+1];
                    size_t o0 = ((size_t)b * FF + co) * HW + p0 + m;
                    out[o0]           = fmaxf(fmaf(d[0], s0, h0), 0.f);
                    out[o0 + HW]      = fmaxf(fmaf(d[1], s1, h1), 0.f);
                    out[o0 + 8]       = fmaxf(fmaf(d[2], s0, h0), 0.f);
                    out[o0 + HW + 8]  = fmaxf(fmaf(d[3], s1, h1), 0.f);
                }
    } else {
        constexpr int FKR = FK ? FK : 1;
        float* sW = (float*)(smem + 2048);            // [co][FK]
        float* sO = sW + 256 * FKR;                   // [FK][128]
        for (int i = tid; i < 256 * FKR; i += 512) sW[i] = fw[i];
        for (int i = tid; i < FKR * 128; i += 512) sO[i] = 0.f;
        __syncthreads();
        #pragma unroll
        for (int mf = 0; mf < 2; mf++)
            #pragma unroll
            for (int hi = 0; hi < 2; hi++) {
                const int mloc = m0 + mf * 16 + group + hi * 8;
                float pk[FKR];
                #pragma unroll
                for (int k = 0; k < FKR; k++) pk[k] = 0.f;
                #pragma unroll
                for (int nb = 0; nb < 4; nb++)
                    #pragma unroll
                    for (int oc = 0; oc < 2; oc++) {
                        const float* d = acc[mf][nb * 2 + oc];
                        int co = n0 + nb * 16 + oc * 8 + tig * 2;
                        float v0 = fmaxf(fmaf(d[hi*2+0], sSc[co],   sSh[co]),   0.f);
                        float v1 = fmaxf(fmaf(d[hi*2+1], sSc[co+1], sSh[co+1]), 0.f);
                        #pragma unroll
                        for (int k = 0; k < FKR; k++)
                            pk[k] = fmaf(v0, sW[co * FKR + k],
                                    fmaf(v1, sW[(co + 1) * FKR + k], pk[k]));
                    }
                #pragma unroll
                for (int k = 0; k < FKR; k++) {
                    pk[k] += __shfl_xor_sync(0xFFFFFFFF, pk[k], 1);
                    pk[k] += __shfl_xor_sync(0xFFFFFFFF, pk[k], 2);
                }
                if (tig == 0)
                    #pragma unroll
                    for (int k = 0; k < FKR; k++)
                        atomicAdd(&sO[k * 128 + mloc], pk[k]);
            }
        __syncthreads();
        for (int i = tid; i < FKR * 128; i += 512) {
            int k = i >> 7, m = i & 127;
            fout[((size_t)b * FKR + k) * HW + p0 + m] = sO[i];
        }
    }
}

// ---------------- head stage 2: 9-tap shift-add + bias ----------------
__global__ __launch_bounds__(256) void k_head2(const float* __restrict__ bias,
                                               float* __restrict__ out) {
    int idx = blockIdx.x * 256 + threadIdx.x;       // BB*16384
    int x = idx & 127, y = (idx >> 7) & 127, b = idx >> 14;
    float s = bias[0];
    #pragma unroll
    for (int ky = 0; ky < 3; ky++) {
        int yy = y + ky - 1;
        if (yy < 0 || yy >= 128) continue;
        #pragma unroll
        for (int kx = 0; kx < 3; kx++) {
            int xx = x + kx - 1;
            if (xx < 0 || xx >= 128) continue;
            s += g_P[(((size_t)b * 9 + ky * 3 + kx) << 14) + yy * 128 + xx];
        }
    }
    out[idx] = s;
}

// ---------------- launch ----------------
extern "C" void kernel_launch(void* const* d_in, const int* in_sizes, int n_in,
                              void* d_out, int out_size)
{
    const float* f1  = (const float*)d_in[0];
    const float* f2  = (const float*)d_in[1];
    const float* f3  = (const float*)d_in[2];
    const float* f4  = (const float*)d_in[3];
    const float* pw  = (const float*)d_in[4];
    const float* lwv = (const float*)d_in[5];
    const float* dww = (const float*)d_in[6];
    const float* bne = (const float*)d_in[7];
    const float* ow1 = (const float*)d_in[8];
    const float* ob1 = (const float*)d_in[9];
    const float* cw1 = (const float*)d_in[10];
    const float* bn1 = (const float*)d_in[11];
    const float* ow2 = (const float*)d_in[12];
    const float* ob2 = (const float*)d_in[13];
    const float* cw2 = (const float*)d_in[14];
    const float* bn2 = (const float*)d_in[15];
    const float* hw  = (const float*)d_in[16];
    const float* hb  = (const float*)d_in[17];
    float* out = (float*)d_out;

    float *p_x1, *p_off1, *p_c1, *p_off2, *p_P;
    uint32_t *p_u1H, *p_u1L, *p_u2H, *p_u2L, *p_w1H, *p_w2H;
    cudaGetSymbolAddress((void**)&p_x1,  g_x1);
    cudaGetSymbolAddress((void**)&p_off1, g_off1);
    cudaGetSymbolAddress((void**)&p_c1,  g_c1);
    cudaGetSymbolAddress((void**)&p_off2, g_off2);
    cudaGetSymbolAddress((void**)&p_P,   g_P);
    cudaGetSymbolAddress((void**)&p_u1H, g_up1H);
    cudaGetSymbolAddress((void**)&p_u1L, g_up1L);
    cudaGetSymbolAddress((void**)&p_u2H, g_up2H);
    cudaGetSymbolAddress((void**)&p_u2L, g_up2L);
    cudaGetSymbolAddress((void**)&p_w1H, g_w1H);
    cudaGetSymbolAddress((void**)&p_w2H, g_w2H);

    cudaFuncSetAttribute(k_conv_mma<0>, cudaFuncAttributeMaxDynamicSharedMemorySize, CM_SMEM);
    cudaFuncSetAttribute(k_conv_mma<9>, cudaFuncAttributeMaxDynamicSharedMemorySize, CM_SMEM);
    cudaFuncSetAttribute(k_fusion_mma,  cudaFuncAttributeMaxDynamicSharedMemorySize, FM_SMEM);
    cudaFuncSetAttribute(k_off,         cudaFuncAttributeMaxDynamicSharedMemorySize, KO_SMEM);

    k_prep_w<<<(2*294912)/256, 256>>>(cw1, cw2);
    k_prep_pw<<<393216/256, 256>>>(pw);
    k_fusion_mma<<<dim3(64, 2), 256, FM_SMEM>>>(f1, f2, f3, f4, lwv);
    k_dw<<<(BB*FF*N0)/256, 256>>>(dww, bne);
    k_off<<<dim3(N0/64, BB), 256, KO_SMEM>>>(p_x1, ow1, ob1, p_off1, N0);
    k_up<<<(BB*128*4*N0)/256, 256>>>(p_x1, p_off1, p_u1H, p_u1L, 32, 32);
    k_conv_mma<0><<<dim3(4*N0/128, BB), 512, CM_SMEM>>>(
        p_u1H, p_u1L, p_w1H, bn1, p_c1, nullptr, nullptr, 64, 6);
    k_off<<<dim3(4*N0/64, BB), 256, KO_SMEM>>>(p_c1, ow2, ob2, p_off2, 4*N0);
    k_up<<<(BB*128*16*N0)/256, 256>>>(p_c1, p_off2, p_u2H, p_u2L, 64, 64);
    k_conv_mma<9><<<dim3(16*N0/128, BB), 512, CM_SMEM>>>(
        p_u2H, p_u2L, p_w2H, bn2, nullptr, hw, p_P, 128, 7);
    k_head2<<<(BB*16384)/256, 256>>>(hb, out);
}

// round 17
// speedup vs baseline: 1.5883x; 1.3048x over previous
#include <cuda_runtime.h>
#include <cuda_bf16.h>
#include <cuda_fp16.h>
#include <cstdint>
#include <math.h>

#define BB 4
#define CC 768
#define FF 256
#define N0 1024

// ---------------- scratch ----------------
__device__ float g_x0 [BB*FF*N0];
__device__ float g_x1 [BB*FF*N0];
__device__ float g_off1[BB*32*N0];
__device__ float g_off2[BB*32*4*N0];
__device__ float g_c1 [BB*FF*4*N0];
__device__ float g_P  [BB*9*16*N0];            // head partial planes
__device__ uint32_t g_up1H[BB*128*4*N0];       // fp16x2 activations (single plane)
__device__ uint32_t g_up2H[BB*128*16*N0];
__device__ uint32_t g_w1H[294912];             // fp16x2 conv weights (single plane)
__device__ uint32_t g_w2H[294912];
__device__ uint32_t g_pwH[393216], g_pwL[393216];  // fusion bf16 hi/lo
__device__ float g_zero4[4] = {0.f, 0.f, 0.f, 0.f};

// ---------------- helpers ----------------
__device__ __forceinline__ uint32_t smem_u32(const void* p) {
    uint32_t a; asm("{ .reg .u64 t; cvta.to.shared.u64 t, %1; cvt.u32.u64 %0, t; }"
                    : "=r"(a) : "l"(p)); return a;
}
#define SWZ(x) ((uint32_t)(x) ^ ((((uint32_t)(x)) >> 3) & 0x70u))

__device__ __forceinline__ void ldsm_x4(uint32_t (&r)[4], uint32_t addr) {
    asm volatile("ldmatrix.sync.aligned.m8n8.x4.shared.b16 {%0,%1,%2,%3}, [%4];"
        : "=r"(r[0]), "=r"(r[1]), "=r"(r[2]), "=r"(r[3]) : "r"(addr));
}
// bf16 mma (fusion)
__device__ __forceinline__ void mma_bf(float* d, const uint32_t* a, const uint32_t* b) {
    asm volatile("mma.sync.aligned.m16n8k16.row.col.f32.bf16.bf16.f32 "
        "{%0,%1,%2,%3}, {%4,%5,%6,%7}, {%8,%9}, {%0,%1,%2,%3};"
        : "+f"(d[0]), "+f"(d[1]), "+f"(d[2]), "+f"(d[3])
        : "r"(a[0]), "r"(a[1]), "r"(a[2]), "r"(a[3]), "r"(b[0]), "r"(b[1]));
}
// fp16 mma (convs)
__device__ __forceinline__ void mma_fp(float* d, const uint32_t* a, const uint32_t* b) {
    asm volatile("mma.sync.aligned.m16n8k16.row.col.f32.f16.f16.f32 "
        "{%0,%1,%2,%3}, {%4,%5,%6,%7}, {%8,%9}, {%0,%1,%2,%3};"
        : "+f"(d[0]), "+f"(d[1]), "+f"(d[2]), "+f"(d[3])
        : "r"(a[0]), "r"(a[1]), "r"(a[2]), "r"(a[3]), "r"(b[0]), "r"(b[1]));
}
__device__ __forceinline__ void split_bf16(float v, __nv_bfloat16& h, __nv_bfloat16& l) {
    h = __float2bfloat16(v);
    l = __float2bfloat16(v - __bfloat162float(h));
}
__device__ __forceinline__ uint32_t pack2bf(__nv_bfloat16 a, __nv_bfloat16 b) {
    __nv_bfloat162 t = __halves2bfloat162(a, b);
    return *(uint32_t*)&t;
}
__device__ __forceinline__ uint32_t pack2h(__half a, __half b) {
    __half2 t = __halves2half2(a, b);
    return *(uint32_t*)&t;
}
#define CP_A4(dst, src)  asm volatile("cp.async.ca.shared.global [%0], [%1], 4;"  :: "r"(dst), "l"(src))
#define CP_A16(dst, src) asm volatile("cp.async.cg.shared.global [%0], [%1], 16;" :: "r"(dst), "l"(src))
#define CP_COMMIT() asm volatile("cp.async.commit_group;" ::: "memory")
#define CP_WAIT0()  asm volatile("cp.async.wait_group 0;" ::: "memory")
#define CP_WAIT1()  asm volatile("cp.async.wait_group 1;" ::: "memory")

// ---------------- conv weight pre-pack: OIHW -> [ch36][co][c2 32] fp16x2 ----------------
__global__ __launch_bounds__(256) void k_prep_w(const float* __restrict__ w1,
                                                const float* __restrict__ w2) {
    int idx = blockIdx.x * 256 + threadIdx.x;
    int which = idx >= 294912;
    int t = which ? idx - 294912 : idx;
    int c2 = t & 31, co = (t >> 5) & 255, ch = t >> 13;
    int kpos = ch >> 2, ci = (ch & 3) * 64 + 2 * c2;
    const float* w = which ? w2 : w1;
    float v0 = w[(co * 256 + ci) * 9 + kpos];
    float v1 = w[(co * 256 + ci + 1) * 9 + kpos];
    (which ? g_w2H : g_w1H)[t] = pack2h(__float2half_rn(v0), __float2half_rn(v1));
}

// ---------------- fusion weight pre-pack (bf16 hi/lo) ----------------
__global__ __launch_bounds__(256) void k_prep_pw(const float* __restrict__ pw) {
    int t = blockIdx.x * 256 + threadIdx.x;
    int c2 = t & 31, co = (t >> 5) & 255, r = t >> 13;
    int l = r / 12, ch = r - l * 12;
    int c = ch * 64 + 2 * c2;
    float v0 = pw[((size_t)l * CC + c) * FF + co];
    float v1 = pw[((size_t)l * CC + c + 1) * FF + co];
    __nv_bfloat16 h0, l0, h1, l1;
    split_bf16(v0, h0, l0); split_bf16(v1, h1, l1);
    g_pwH[t] = pack2bf(h0, h1);
    g_pwL[t] = pack2bf(l0, l1);
}

// ---------------- fusion GEMM: HMMA bf16 3-term, GELU + weighted layer sum ----------------
#define FM_SMEM (49152 + 1024)
__global__ __launch_bounds__(256) void k_fusion_mma(
    const float* __restrict__ fa, const float* __restrict__ fb,
    const float* __restrict__ fc, const float* __restrict__ fd,
    const float* __restrict__ lwp)
{
    extern __shared__ char smem_raw[];
    const uint32_t sb0 = smem_u32(smem_raw);
    const uint32_t sa = (sb0 + 1023u) & ~1023u;
    char* smem = smem_raw + (sa - sb0);
    const int tid = threadIdx.x, wid = tid >> 5, lane = tid & 31;
    const int mt0 = blockIdx.x * 64;
    const int f0  = blockIdx.y * 128;
    const int m0 = (wid & 1) * 32;
    const int n0 = (wid >> 1) * 32;

    char* Ah = smem;          char* Al = smem + 8192;
    char* Bh = smem + 16384;  char* Bl = smem + 32768;
    const uint32_t aAh = sa, aAl = sa + 8192, aBh = sa + 16384, aBl = sa + 32768;

    float w0 = lwp[0], w1 = lwp[1], w2 = lwp[2], w3 = lwp[3];
    float mx = fmaxf(fmaxf(w0, w1), fmaxf(w2, w3));
    float e0 = expf(w0-mx), e1 = expf(w1-mx), e2 = expf(w2-mx), e3 = expf(w3-mx);
    float inv = 1.0f / (e0+e1+e2+e3);
    float lw[4] = {e0*inv, e1*inv, e2*inv, e3*inv};
    const float* fs[4] = {fa, fb, fc, fd};

    const int aRow = lane & 15, aCol = (lane >> 4) * 8;
    const int bRow = (lane & 7) + ((lane >> 4) << 3);
    const int bCol = ((lane >> 3) & 1) * 8;

    float acc[2][4][4], oacc[2][4][4];
    #pragma unroll
    for (int i = 0; i < 2; i++)
        #pragma unroll
        for (int j = 0; j < 4; j++)
            #pragma unroll
            for (int q = 0; q < 4; q++) { acc[i][j][q] = 0.f; oacc[i][j][q] = 0.f; }

    for (int l = 0; l < 4; l++) {
        const float* fl = fs[l];
        for (int ch = 0; ch < 12; ch++) {
            const int kc0 = ch * 64;
            __syncthreads();
            for (int idx = tid; idx < 64 * 32; idx += 256) {
                int m = idx & 63, c2 = idx >> 6;
                int pix = mt0 + m, b = pix >> 10, n = pix & 1023;
                const float* ip = fl + ((size_t)b * CC + kc0 + 2 * c2) * N0 + n;
                float a0 = ip[0], a1 = ip[N0];
                __nv_bfloat16 h0, l0, h1, l1;
                split_bf16(a0, h0, l0); split_bf16(a1, h1, l1);
                uint32_t sw = SWZ(m * 128 + c2 * 4);
                *(uint32_t*)(Ah + sw) = pack2bf(h0, h1);
                *(uint32_t*)(Al + sw) = pack2bf(l0, l1);
            }
            for (int idx = tid; idx < 128 * 32; idx += 256) {
                int co = idx & 127, c2 = idx >> 7;
                size_t src = ((size_t)(l * 12 + ch) * 256 + f0 + co) * 32 + c2;
                uint32_t sw = SWZ(co * 128 + c2 * 4);
                *(uint32_t*)(Bh + sw) = g_pwH[src];
                *(uint32_t*)(Bl + sw) = g_pwL[src];
            }
            __syncthreads();
            #pragma unroll
            for (int ks = 0; ks < 4; ks++) {
                const int k0 = ks * 16;
                uint32_t ah[2][4], al[2][4], bh[2][4], bl[2][4];
                #pragma unroll
                for (int mf = 0; mf < 2; mf++) {
                    uint32_t off = SWZ((m0 + mf * 16 + aRow) * 128 + (k0 + aCol) * 2);
                    ldsm_x4(ah[mf], aAh + off);
                    ldsm_x4(al[mf], aAl + off);
                }
                #pragma unroll
                for (int nb = 0; nb < 2; nb++) {
                    uint32_t off = SWZ((n0 + nb * 16 + bRow) * 128 + (k0 + bCol) * 2);
                    ldsm_x4(bh[nb], aBh + off);
                    ldsm_x4(bl[nb], aBl + off);
                }
                #pragma unroll
                for (int mf = 0; mf < 2; mf++)
                    #pragma unroll
                    for (int nb = 0; nb < 2; nb++)
                        #pragma unroll
                        for (int oc = 0; oc < 2; oc++) {
                            float* d = acc[mf][nb * 2 + oc];
                            mma_bf(d, ah[mf], &bh[nb][oc * 2]);
                            mma_bf(d, ah[mf], &bl[nb][oc * 2]);
                            mma_bf(d, al[mf], &bh[nb][oc * 2]);
                        }
            }
        }
        #pragma unroll
        for (int i = 0; i < 2; i++)
            #pragma unroll
            for (int j = 0; j < 4; j++)
                #pragma unroll
                for (int q = 0; q < 4; q++) {
                    float v = acc[i][j][q];
                    acc[i][j][q] = 0.f;
                    float g = 0.5f * v * (1.0f + erff(v * 0.70710678118654752f));
                    oacc[i][j][q] = fmaf(lw[l], g, oacc[i][j][q]);
                }
    }
    const int group = lane >> 2, tig = lane & 3;
    #pragma unroll
    for (int mf = 0; mf < 2; mf++)
        #pragma unroll
        for (int nb = 0; nb < 2; nb++)
            #pragma unroll
            for (int oc = 0; oc < 2; oc++) {
                const float* d = oacc[mf][nb * 2 + oc];
                int co = f0 + n0 + nb * 16 + oc * 8 + tig * 2;
                int m  = mt0 + m0 + mf * 16 + group;
                int b = m >> 10, n = m & 1023;
                size_t o0 = ((size_t)b * FF + co) * N0 + n;
                g_x0[o0]          = d[0];
                g_x0[o0 + N0]     = d[1];
                g_x0[o0 + 8]      = d[2];
                g_x0[o0 + N0 + 8] = d[3];
            }
}

// ---------------- depthwise + BN + residual ----------------
__global__ __launch_bounds__(256) void k_dw(const float* __restrict__ dww,
                                            const float* __restrict__ bn) {
    int idx = blockIdx.x * 256 + threadIdx.x;
    int w = idx & 31, h = (idx >> 5) & 31, f = (idx >> 10) & 255, b = idx >> 18;
    const float* pl = g_x0 + ((size_t)b*FF + f) * N0;
    float acc = 0.f;
    #pragma unroll
    for (int dy = 0; dy < 3; dy++) {
        int yy = h + dy - 1; if (yy < 0 || yy >= 32) continue;
        #pragma unroll
        for (int dx = 0; dx < 3; dx++) {
            int xx = w + dx - 1; if (xx < 0 || xx >= 32) continue;
            acc = fmaf(pl[yy*32+xx], dww[f*9+dy*3+dx], acc);
        }
    }
    float bnv = (acc - bn[512+f]) * bn[f] * rsqrtf(bn[768+f] + 1e-5f) + bn[256+f];
    g_x1[idx] = fmaxf(bnv + pl[h*32+w], 0.f);
}

// ---------------- offset conv 1x1 (256->32): 64px x 4 k-split groups ----------------
#define KO_SMEM (32768 + 33792)
__global__ __launch_bounds__(256) void k_off(const float* __restrict__ in,
    const float* __restrict__ ow, const float* __restrict__ ob,
    float* __restrict__ out, int HW) {
    extern __shared__ float ko[];
    float (*wT)[32] = (float(*)[32])ko;
    float (*sred)[64][33] = (float(*)[64][33])(ko + 8192);
    const int tid = threadIdx.x;
    for (int idx = tid; idx < 8192; idx += 256)
        wT[idx & 255][idx >> 8] = ow[(idx >> 8) * 256 + (idx & 255)];
    __syncthreads();
    const int px = tid & 63, grp = tid >> 6;
    const int hw = blockIdx.x * 64 + px, b = blockIdx.y;
    float acc[32];
    #pragma unroll
    for (int k = 0; k < 32; k++) acc[k] = 0.f;
    const float* ip = in + ((size_t)b * FF + grp * 64) * HW + hw;
    #pragma unroll 4
    for (int c = 0; c < 64; c++) {
        float v = ip[(size_t)c * HW];
        const float* wr = wT[grp * 64 + c];
        #pragma unroll
        for (int k8 = 0; k8 < 8; k8++) {
            float4 w4 = *(const float4*)&wr[k8 * 4];
            acc[k8*4+0]=fmaf(v,w4.x,acc[k8*4+0]); acc[k8*4+1]=fmaf(v,w4.y,acc[k8*4+1]);
            acc[k8*4+2]=fmaf(v,w4.z,acc[k8*4+2]); acc[k8*4+3]=fmaf(v,w4.w,acc[k8*4+3]);
        }
    }
    #pragma unroll
    for (int k = 0; k < 32; k++) sred[grp][px][k] = acc[k];
    __syncthreads();
    for (int idx = tid; idx < 2048; idx += 256) {
        int k = idx & 31, p = idx >> 5;
        float s = sred[0][p][k] + sred[1][p][k] + sred[2][p][k] + sred[3][p][k] + ob[k];
        out[((size_t)b * 32 + k) * HW + blockIdx.x * 64 + p] = s;
    }
}

// ---------------- DySample bilinear 2x -> packed fp16 channel-pair planes ----------------
__global__ __launch_bounds__(256) void k_up(const float* __restrict__ in,
    const float* __restrict__ off, uint32_t* __restrict__ outH, int H, int W) {
    int Ho = 2*H, Wo = 2*W;
    int idx = blockIdx.x * 256 + threadIdx.x;
    int X = idx % Wo; int t = idx / Wo;
    int Y = t % Ho;   t /= Ho;
    int c2 = t & 127, b = t >> 7;
    int cc0 = 2 * c2, g = cc0 >> 6;
    int h = Y >> 1, i = Y & 1, w = X >> 1, j = X & 1;
    int offc = (g << 2) + (i << 1) + j, HW = H * W;
    float ox = off[((size_t)b*32 + offc)*HW + h*W + w] * 0.25f + (j ? 0.25f : -0.25f);
    float oy = off[((size_t)b*32 + 16 + offc)*HW + h*W + w] * 0.25f + (i ? 0.25f : -0.25f);
    float px = fminf(fmaxf((float)w + ox, 0.f), (float)(W-1));
    float py = fminf(fmaxf((float)h + oy, 0.f), (float)(H-1));
    int x0 = (int)floorf(px), y0 = (int)floorf(py);
    float wx = px - x0, wy = py - y0;
    int x1 = min(x0+1, W-1), y1 = min(y0+1, H-1);
    const float* pl = in + ((size_t)b*FF + cc0)*HW;
    float w00 = (1.f-wy)*(1.f-wx), w01 = (1.f-wy)*wx, w10 = wy*(1.f-wx), w11 = wy*wx;
    float va = pl[y0*W+x0]*w00 + pl[y0*W+x1]*w01 + pl[y1*W+x0]*w10 + pl[y1*W+x1]*w11;
    const float* pl1 = pl + HW;
    float vb = pl1[y0*W+x0]*w00 + pl1[y0*W+x1]*w01 + pl1[y1*W+x0]*w10 + pl1[y1*W+x1]*w11;
    size_t o = ((size_t)b * 128 + c2) * (Ho * Wo) + Y * Wo + X;
    outH[o] = pack2h(__float2half_rn(va), __float2half_rn(vb));
}

// ---------------- HMMA fp16 single-term implicit-GEMM conv ----------------
// per stage: Ah@0(16K) Bh@16384(32K) = 49152
// FK=0: plain BN+ReLU epilogue.  FK=9: no main write; fused head 1x1 -> P planes.
#define STG 49152
#define CM_SMEM (2048 + 2*STG + 1024)
template<int FK>
__global__ __launch_bounds__(512) void k_conv_mma(
    const uint32_t* __restrict__ upH, const uint32_t* __restrict__ wH,
    const float* __restrict__ bn, float* __restrict__ out,
    const float* __restrict__ fw, float* __restrict__ fout, int W, int logW)
{
    extern __shared__ char smem_raw[];
    const uint32_t sb0 = smem_u32(smem_raw);
    const uint32_t sa = (sb0 + 1023u) & ~1023u;
    char* smem = smem_raw + (sa - sb0);
    const int tid = threadIdx.x, wid = tid >> 5, lane = tid & 31;
    const int HW = W * W;
    const int b = blockIdx.y;
    const int p0 = blockIdx.x * 128;

    float* sSc = (float*)(smem);
    float* sSh = (float*)(smem + 1024);
    if (tid < 256) {
        float sc = bn[tid] * rsqrtf(bn[768 + tid] + 1e-5f);
        sSc[tid] = sc;
        sSh[tid] = bn[256 + tid] - bn[512 + tid] * sc;
    }

    const uint32_t aStage = sa + 2048;
    const uint64_t zsrc = __cvta_generic_to_global(&g_zero4[0]);

    auto fill = [&](int ch, int s) {
        const int kpos = ch >> 2;
        const int cb2 = (ch & 3) * 32;
        const int ky = kpos / 3 - 1, kx = kpos % 3 - 1;
        const uint32_t stg = aStage + s * STG;
        // A: 128 px x 32 c2, single fp16 plane
        #pragma unroll
        for (int r = 0; r < 8; r++) {
            int idx = tid + r * 512;
            int m = idx & 127, c2 = idx >> 7;
            int pix = p0 + m;
            int y = (pix >> logW) + ky, x = (pix & (W - 1)) + kx;
            bool ok = (y >= 0 && y < W && x >= 0 && x < W);
            uint64_t srcH = zsrc;
            if (ok) {
                size_t e = ((size_t)b * 128 + cb2 + c2) * HW + y * W + x;
                srcH = __cvta_generic_to_global(&upH[e]);
            }
            uint32_t sw = SWZ(m * 128 + c2 * 4);
            CP_A4(stg + sw, srcH);
        }
        // B: 256 co x 32 c2, single fp16 plane, 16B quads
        #pragma unroll
        for (int r = 0; r < 4; r++) {
            int q = tid + r * 512;                   // 2048 quads
            int co = q >> 3, c2q = q & 7;
            size_t src = ((size_t)ch * 256 + co) * 32 + c2q * 4;
            uint32_t sw = SWZ(co * 128 + c2q * 16);
            CP_A16(stg + 16384 + sw, __cvta_generic_to_global(&wH[src]));
        }
    };

    const int m0 = (wid & 3) * 32;
    const int n0 = (wid >> 2) * 64;
    const int aRow = lane & 15, aCol = (lane >> 4) * 8;
    const int bRow = (lane & 7) + ((lane >> 4) << 3);
    const int bCol = ((lane >> 3) & 1) * 8;

    float acc[2][8][4];
    #pragma unroll
    for (int i = 0; i < 2; i++)
        #pragma unroll
        for (int j = 0; j < 8; j++)
            #pragma unroll
            for (int q = 0; q < 4; q++) acc[i][j][q] = 0.f;

    fill(0, 0); CP_COMMIT();

    for (int ch = 0; ch < 36; ch++) {
        if (ch < 35) { fill(ch + 1, (ch + 1) & 1); CP_COMMIT(); CP_WAIT1(); }
        else         { CP_WAIT0(); }
        __syncthreads();
        const uint32_t stg = aStage + (ch & 1) * STG;
        const uint32_t aAh = stg, aBh = stg + 16384;
        #pragma unroll
        for (int ks = 0; ks < 4; ks++) {
            const int k0 = ks * 16;
            uint32_t ah[2][4], bh[4][4];
            #pragma unroll
            for (int mf = 0; mf < 2; mf++) {
                uint32_t off = SWZ((m0 + mf * 16 + aRow) * 128 + (k0 + aCol) * 2);
                ldsm_x4(ah[mf], aAh + off);
            }
            #pragma unroll
            for (int nb = 0; nb < 4; nb++) {
                uint32_t off = SWZ((n0 + nb * 16 + bRow) * 128 + (k0 + bCol) * 2);
                ldsm_x4(bh[nb], aBh + off);
            }
            #pragma unroll
            for (int mf = 0; mf < 2; mf++)
                #pragma unroll
                for (int nb = 0; nb < 4; nb++)
                    #pragma unroll
                    for (int oc = 0; oc < 2; oc++)
                        mma_fp(acc[mf][nb * 2 + oc], ah[mf], &bh[nb][oc * 2]);
        }
        __syncthreads();
    }

    const int group = lane >> 2, tig = lane & 3;
    if constexpr (FK == 0) {
        #pragma unroll
        for (int mf = 0; mf < 2; mf++)
            #pragma unroll
            for (int nb = 0; nb < 4; nb++)
                #pragma unroll
                for (int oc = 0; oc < 2; oc++) {
                    const float* d = acc[mf][nb * 2 + oc];
                    int co = n0 + nb * 16 + oc * 8 + tig * 2;
                    int m  = m0 + mf * 16 + group;
                    float s0 = sSc[co], h0 = sSh[co], s1 = sSc[co+1], h1 = sSh[co+1];
                    size_t o0 = ((size_t)b * FF + co) * HW + p0 + m;
                    out[o0]           = fmaxf(fmaf(d[0], s0, h0), 0.f);
                    out[o0 + HW]      = fmaxf(fmaf(d[1], s1, h1), 0.f);
                    out[o0 + 8]       = fmaxf(fmaf(d[2], s0, h0), 0.f);
                    out[o0 + HW + 8]  = fmaxf(fmaf(d[3], s1, h1), 0.f);
                }
    } else {
        constexpr int FKR = FK ? FK : 1;
        float* sW = (float*)(smem + 2048);            // [co][FK]
        float* sO = sW + 256 * FKR;                   // [FK][128]
        for (int i = tid; i < 256 * FKR; i += 512) sW[i] = fw[i];
        for (int i = tid; i < FKR * 128; i += 512) sO[i] = 0.f;
        __syncthreads();
        #pragma unroll
        for (int mf = 0; mf < 2; mf++)
            #pragma unroll
            for (int hi = 0; hi < 2; hi++) {
                const int mloc = m0 + mf * 16 + group + hi * 8;
                float pk[FKR];
                #pragma unroll
                for (int k = 0; k < FKR; k++) pk[k] = 0.f;
                #pragma unroll
                for (int nb = 0; nb < 4; nb++)
                    #pragma unroll
                    for (int oc = 0; oc < 2; oc++) {
                        const float* d = acc[mf][nb * 2 + oc];
                        int co = n0 + nb * 16 + oc * 8 + tig * 2;
                        float v0 = fmaxf(fmaf(d[hi*2+0], sSc[co],   sSh[co]),   0.f);
                        float v1 = fmaxf(fmaf(d[hi*2+1], sSc[co+1], sSh[co+1]), 0.f);
                        #pragma unroll
                        for (int k = 0; k < FKR; k++)
                            pk[k] = fmaf(v0, sW[co * FKR + k],
                                    fmaf(v1, sW[(co + 1) * FKR + k], pk[k]));
                    }
                #pragma unroll
                for (int k = 0; k < FKR; k++) {
                    pk[k] += __shfl_xor_sync(0xFFFFFFFF, pk[k], 1);
                    pk[k] += __shfl_xor_sync(0xFFFFFFFF, pk[k], 2);
                }
                if (tig == 0)
                    #pragma unroll
                    for (int k = 0; k < FKR; k++)
                        atomicAdd(&sO[k * 128 + mloc], pk[k]);
            }
        __syncthreads();
        for (int i = tid; i < FKR * 128; i += 512) {
            int k = i >> 7, m = i & 127;
            fout[((size_t)b * FKR + k) * HW + p0 + m] = sO[i];
        }
    }
}

// ---------------- head stage 2: 9-tap shift-add + bias ----------------
__global__ __launch_bounds__(256) void k_head2(const float* __restrict__ bias,
                                               float* __restrict__ out) {
    int idx = blockIdx.x * 256 + threadIdx.x;       // BB*16384
    int x = idx & 127, y = (idx >> 7) & 127, b = idx >> 14;
    float s = bias[0];
    #pragma unroll
    for (int ky = 0; ky < 3; ky++) {
        int yy = y + ky - 1;
        if (yy < 0 || yy >= 128) continue;
        #pragma unroll
        for (int kx = 0; kx < 3; kx++) {
            int xx = x + kx - 1;
            if (xx < 0 || xx >= 128) continue;
            s += g_P[(((size_t)b * 9 + ky * 3 + kx) << 14) + yy * 128 + xx];
        }
    }
    out[idx] = s;
}

// ---------------- launch ----------------
extern "C" void kernel_launch(void* const* d_in, const int* in_sizes, int n_in,
                              void* d_out, int out_size)
{
    const float* f1  = (const float*)d_in[0];
    const float* f2  = (const float*)d_in[1];
    const float* f3  = (const float*)d_in[2];
    const float* f4  = (const float*)d_in[3];
    const float* pw  = (const float*)d_in[4];
    const float* lwv = (const float*)d_in[5];
    const float* dww = (const float*)d_in[6];
    const float* bne = (const float*)d_in[7];
    const float* ow1 = (const float*)d_in[8];
    const float* ob1 = (const float*)d_in[9];
    const float* cw1 = (const float*)d_in[10];
    const float* bn1 = (const float*)d_in[11];
    const float* ow2 = (const float*)d_in[12];
    const float* ob2 = (const float*)d_in[13];
    const float* cw2 = (const float*)d_in[14];
    const float* bn2 = (const float*)d_in[15];
    const float* hw  = (const float*)d_in[16];
    const float* hb  = (const float*)d_in[17];
    float* out = (float*)d_out;

    float *p_x1, *p_off1, *p_c1, *p_off2, *p_P;
    uint32_t *p_u1H, *p_u2H, *p_w1H, *p_w2H;
    cudaGetSymbolAddress((void**)&p_x1,  g_x1);
    cudaGetSymbolAddress((void**)&p_off1, g_off1);
    cudaGetSymbolAddress((void**)&p_c1,  g_c1);
    cudaGetSymbolAddress((void**)&p_off2, g_off2);
    cudaGetSymbolAddress((void**)&p_P,   g_P);
    cudaGetSymbolAddress((void**)&p_u1H, g_up1H);
    cudaGetSymbolAddress((void**)&p_u2H, g_up2H);
    cudaGetSymbolAddress((void**)&p_w1H, g_w1H);
    cudaGetSymbolAddress((void**)&p_w2H, g_w2H);

    cudaFuncSetAttribute(k_conv_mma<0>, cudaFuncAttributeMaxDynamicSharedMemorySize, CM_SMEM);
    cudaFuncSetAttribute(k_conv_mma<9>, cudaFuncAttributeMaxDynamicSharedMemorySize, CM_SMEM);
    cudaFuncSetAttribute(k_fusion_mma,  cudaFuncAttributeMaxDynamicSharedMemorySize, FM_SMEM);
    cudaFuncSetAttribute(k_off,         cudaFuncAttributeMaxDynamicSharedMemorySize, KO_SMEM);

    k_prep_w<<<(2*294912)/256, 256>>>(cw1, cw2);
    k_prep_pw<<<393216/256, 256>>>(pw);
    k_fusion_mma<<<dim3(64, 2), 256, FM_SMEM>>>(f1, f2, f3, f4, lwv);
    k_dw<<<(BB*FF*N0)/256, 256>>>(dww, bne);
    k_off<<<dim3(N0/64, BB), 256, KO_SMEM>>>(p_x1, ow1, ob1, p_off1, N0);
    k_up<<<(BB*128*4*N0)/256, 256>>>(p_x1, p_off1, p_u1H, 32, 32);
    k_conv_mma<0><<<dim3(4*N0/128, BB), 512, CM_SMEM>>>(
        p_u1H, p_w1H, bn1, p_c1, nullptr, nullptr, 64, 6);
    k_off<<<dim3(4*N0/64, BB), 256, KO_SMEM>>>(p_c1, ow2, ob2, p_off2, 4*N0);
    k_up<<<(BB*128*16*N0)/256, 256>>>(p_c1, p_off2, p_u2H, 64, 64);
    k_conv_mma<9><<<dim3(16*N0/128, BB), 512, CM_SMEM>>>(
        p_u2H, p_w2H, bn2, nullptr, hw, p_P, 128, 7);
    k_head2<<<(BB*16384)/256, 256>>>(hb, out);
}